// round 12
// baseline (speedup 1.0000x reference)
#include <cuda_runtime.h>
#include <cuda_fp16.h>
#include <cstdint>
#include <math.h>

#define SEQ   2048
#define HD    128
#define NROT  64
#define NROWS (4 * 2048 * 32)     // 262144 rows of 128
#define TILES64 (NROWS / 64)      // 4096 tiles of 64 rows
#define GRID  304                 // 2 CTAs per SM
#define NTHREADS 256

// main-kernel SMEM layout (bytes) — 64KB per CTA
#define SMEM_A    0               // 2 bufs x 16KB (fp16 x-tile, 64 rows)
#define SMEM_ST   32768           // 32KB f32 epilogue stage
#define SMEM_SZ   65536

// ---------------- device globals (allocation-free scratch) ----------------
// B pack: uint4 [kt][wn][c2][lane]; uint4 = (b0,b1) for ntg=wn*4+c2*2 and ntg+1
__device__ uint4  g_Bp[8 * 4 * 2 * 32];
__device__ float2 g_SC[SEQ * 64];             // (sin, cos) per (pos, freq)

// ---------------- helpers ----------------
__device__ __forceinline__ uint32_t smem_u32(const void* p) {
    uint32_t a;
    asm("{ .reg .u64 t; cvta.to.shared.u64 t, %1; cvt.u32.u64 %0, t; }" : "=r"(a) : "l"(p));
    return a;
}

#define LDMATRIX_X4(r, addr) \
    asm volatile("ldmatrix.sync.aligned.m8n8.x4.shared.b16 {%0,%1,%2,%3}, [%4];" \
        : "=r"((r)[0]), "=r"((r)[1]), "=r"((r)[2]), "=r"((r)[3]) : "r"(addr))

#define MMA16816(d, a, b0v, b1v) \
    asm volatile("mma.sync.aligned.m16n8k16.row.col.f32.f16.f16.f32 " \
        "{%0,%1,%2,%3}, {%4,%5,%6,%7}, {%8,%9}, {%0,%1,%2,%3};" \
        : "+f"((d)[0]), "+f"((d)[1]), "+f"((d)[2]), "+f"((d)[3]) \
        : "r"((a)[0]), "r"((a)[1]), "r"((a)[2]), "r"((a)[3]), "r"(b0v), "r"(b1v))

// ---------------- fused prep kernel ----------------
// blocks 0..63 : fold rotations -> G, compute 2 M columns, pack B fragments
// blocks 64..95: fill the (pos, freq) sin/cos table
__global__ void prep_kernel(const float* __restrict__ thetas,
                            const float* __restrict__ pairs,
                            const float* __restrict__ scale,
                            const float* __restrict__ Rm,
                            const float* __restrict__ inv_freq) {
    const int tid = threadIdx.x;

    if (blockIdx.x >= 64) {
        int base = (blockIdx.x - 64) * 256 + tid;    // 0..8191
        #pragma unroll
        for (int r = 0; r < 16; r++) {
            int e = base + r * 8192;
            int s = e >> 6, d = e & 63;
            float a = (float)s * inv_freq[d];
            float sv, cv;
            sincosf(a, &sv, &cv);
            g_SC[e] = make_float2(sv, cv);
        }
        return;
    }

    extern __shared__ float ps[];
    float (*G)[HD + 1] = (float (*)[HD + 1])ps;                 // [128][129]
    float (*Mc)[2]     = (float (*)[2])(ps + 128 * (HD + 1));   // [128][2]
    float* cs = ps + 128 * (HD + 1) + 256;       // cos[64]
    float* sn = cs + 64;                         // sin[64]
    int*   ij = (int*)(sn + 64);                 // i[64], j[64]

    if (tid < 64) {
        float th = thetas[tid] * scale[0];
        float s, c;
        sincosf(th, &s, &c);
        cs[tid] = c; sn[tid] = s;
        ij[tid]      = (int)pairs[2 * tid];
        ij[64 + tid] = (int)pairs[2 * tid + 1];
    }
    __syncthreads();

    if (tid < 128) {
        const int t = tid;
        #pragma unroll
        for (int c = 0; c < HD; c++) G[t][c] = (t == c) ? 1.f : 0.f;
        for (int k = 0; k < NROT; k++) {
            int   i   = ij[k];
            int   j   = ij[64 + k];
            float cth = cs[k], sth = sn[k];
            float gi = G[t][i], gj = G[t][j];
            if (i == j) { G[t][i] = gi * cth; }
            else { G[t][i] = gi * cth + gj * sth; G[t][j] = -gi * sth + gj * cth; }
        }
    }
    __syncthreads();

    {
        const int k  = tid >> 1;
        const int nl = tid & 1;
        const int n  = blockIdx.x * 2 + nl;
        float acc = 0.f;
        #pragma unroll 8
        for (int j = 0; j < HD; j++) acc += G[k][j] * Rm[j * HD + n];
        Mc[k][nl] = acc;
    }
    __syncthreads();

    // pack: 64 entries per block (2 n x 8 kt x 4 tq), fp16
    if (tid < 64) {
        const int nl  = tid >> 5;
        const int kt  = (tid >> 2) & 7;
        const int tq  = tid & 3;
        const int n   = blockIdx.x * 2 + nl;
        const int ntg = n >> 3;
        const int wn  = ntg >> 2;
        const int c2  = (ntg >> 1) & 1;
        const int half = ntg & 1;
        const int lane = (n & 7) * 4 + tq;
        const int k0  = kt * 16 + tq * 2;
        uint32_t w[4];
        #pragma unroll
        for (int e = 0; e < 4; e++) {
            float v = Mc[k0 + (e >> 1) * 8 + (e & 1)][nl];
            __half h = __float2half_rn(v);
            w[e] = (uint32_t)*(uint16_t*)&h;
        }
        uint2* bp2 = (uint2*)g_Bp;
        int idx = ((((kt * 4 + wn) * 2 + c2) * 32 + lane)) * 2 + half;
        bp2[idx] = make_uint2(w[0] | (w[1] << 16), w[2] | (w[3] << 16));
    }
}

// ---------------- main kernel ----------------
// A tile SMEM layout (fp16, 16KB, 64 rows): row-major 256B/row, 16B chunks
// XOR-swizzled per 8-row group.

__device__ __forceinline__ void convert_one(float4 v, int g, uint32_t abase) {
    int r = g >> 5;
    int c = g & 31;
    __half2 p01 = __floats2half2_rn(v.x, v.y);
    __half2 p23 = __floats2half2_rn(v.z, v.w);
    uint32_t h01 = *(uint32_t*)&p01;
    uint32_t h23 = *(uint32_t*)&p23;
    uint32_t off = ((uint32_t)r << 8) + (((((uint32_t)c >> 1) ^ (r & 7)) & 15) << 4)
                 + ((c & 1) << 3);
    asm volatile("st.shared.v2.b32 [%0], {%1, %2};" :: "r"(abase + off), "r"(h01), "r"(h23));
}

__global__ void __launch_bounds__(NTHREADS, 2)
rotary_mma(const float* __restrict__ x, float* __restrict__ out) {
    extern __shared__ char smem[];
    const uint32_t sb = smem_u32(smem);
    const int tid  = threadIdx.x;
    const int bid  = blockIdx.x;
    const int warp = tid >> 5;
    const int lane = tid & 31;
    const int wm   = warp >> 2;          // 0..1 : 32-row strip (= seq-pos slot)
    const int wn   = warp & 3;           // 0..3 : 32-col strip
    const int gq   = lane >> 2;          // 0..7
    const int tq   = lane & 3;           // 0..3

    // B fragments: loop-invariant -> load once into 16 uint4 registers
    uint4 Breg[8][2];
    #pragma unroll
    for (int kt = 0; kt < 8; kt++)
        #pragma unroll
        for (int c2 = 0; c2 < 2; c2++)
            Breg[kt][c2] = g_Bp[(((kt * 4 + wn) * 2 + c2) * 32) + lane];

    const int nt = (TILES64 - bid + GRID - 1) / GRID;
    const float4* x4 = (const float4*)x;
    float4*       o4 = (float4*)out;

    // ldmatrix per-thread address pieces
    const int lr = lane & 15;
    const int lc = lane >> 4;
    const uint32_t sw = lr & 7;
    uint32_t rowoff[2];
    rowoff[0] = (uint32_t)(wm * 32 + lr) << 8;
    rowoff[1] = (uint32_t)(wm * 32 + 16 + lr) << 8;

    // prologue: convert tile 0 into A[0]
    {
        const float4* xs = x4 + (size_t)bid * 2048;
        #pragma unroll
        for (int i = 0; i < 8; i++)
            convert_one(xs[tid + i * NTHREADS], tid + i * NTHREADS, sb + SMEM_A);
    }
    __syncthreads();

    for (int it = 0; it < nt; it++) {
        const int buf  = it & 1;
        const int tile = bid + it * GRID;
        const uint32_t abase = sb + SMEM_A + (uint32_t)buf * 16384;
        const uint32_t anext = sb + SMEM_A + (uint32_t)(buf ^ 1) * 16384;
        const bool have_next = (it + 1 < nt);

        // sin/cos for this warp's position + this thread's 4 freq columns
        float2 scv[4];
        {
            int pos = ((tile << 1) + wm) & (SEQ - 1);
            const float2* scp = g_SC + pos * 64 + wn * 16 + tq;
            #pragma unroll
            for (int n = 0; n < 4; n++) scv[n] = scp[n * 4];
        }

        float acc[2][4][4];
        #pragma unroll
        for (int m = 0; m < 2; m++)
            #pragma unroll
            for (int n = 0; n < 4; n++)
                #pragma unroll
                for (int e = 0; e < 4; e++) acc[m][n][e] = 0.f;

        // pipelined next-tile fetch: ring of 4 float4
        const float4* xs = x4 + (size_t)(tile + GRID) * 2048;
        float4 q[4];
        if (have_next) {
            #pragma unroll
            for (int c = 0; c < 4; c++) q[c] = xs[tid + c * NTHREADS];
        }

        #pragma unroll
        for (int kt = 0; kt < 8; kt++) {
            uint32_t A2[2][4];
            const uint32_t choff = ((((uint32_t)(kt * 2 + lc)) ^ sw) & 15) << 4;
            #pragma unroll
            for (int m = 0; m < 2; m++)
                LDMATRIX_X4(A2[m], abase + rowoff[m] + choff);
            #pragma unroll
            for (int c2 = 0; c2 < 2; c2++) {
                uint4 bq = Breg[kt][c2];
                #pragma unroll
                for (int m = 0; m < 2; m++) {
                    MMA16816(acc[m][c2 * 2],     A2[m], bq.x, bq.y);
                    MMA16816(acc[m][c2 * 2 + 1], A2[m], bq.z, bq.w);
                }
            }
            if (have_next) {
                convert_one(q[kt & 3], tid + kt * NTHREADS, anext);
                if (kt < 4) q[kt & 3] = xs[tid + (kt + 4) * NTHREADS];
            }
        }
        __syncthreads();   // A[buf^1] writes done; stage copy-out(it-1) done

        // RoPE + staged transpose (32KB stage, 64 rows)
        {
            float* stage = (float*)(smem + SMEM_ST);
            #pragma unroll
            for (int m = 0; m < 2; m++) {
                #pragma unroll
                for (int h = 0; h < 2; h++) {
                    int row = wm * 32 + m * 16 + h * 8 + gq;
                    int sw2 = row & 7;
                    float* rp = stage + row * 128 + tq;
                    #pragma unroll
                    for (int n = 0; n < 4; n++) {
                        float e = acc[m][n][h * 2];
                        float o = acc[m][n][h * 2 + 1];
                        float s = scv[n].x, c = scv[n].y;
                        int c4 = wn * 4 + n;
                        rp[((c4       ^ sw2) << 2)] = e * c - o * s;   // col d
                        rp[(((16 + c4) ^ sw2) << 2)] = e * s + o * c;  // col 64+d
                    }
                }
            }
        }
        __syncthreads();

        // coalesced copy stage -> out
        {
            const float* stage = (const float*)(smem + SMEM_ST);
            float4* od = o4 + (size_t)tile * 2048;
            #pragma unroll
            for (int i = 0; i < 8; i++) {
                int g = tid + i * NTHREADS;
                int row = g >> 5, c4 = g & 31;
                od[g] = *(const float4*)&stage[row * 128 + ((c4 ^ (row & 7)) << 2)];
            }
        }
        // no sync: next iteration's post-MMA sync orders stage reuse
    }
}

// ---------------- launcher ----------------
extern "C" void kernel_launch(void* const* d_in, const int* in_sizes, int n_in,
                              void* d_out, int out_size) {
    const float* x        = (const float*)d_in[0];
    const float* thetas   = (const float*)d_in[1];
    const float* pairs    = (const float*)d_in[2];
    const float* scale    = (const float*)d_in[3];
    const float* Rm       = (const float*)d_in[4];
    const float* inv_freq = (const float*)d_in[5];
    float*       out      = (float*)d_out;
    (void)in_sizes; (void)n_in; (void)out_size;

    const int prep_smem = (128 * (HD + 1) + 256 + 128 + 128) * 4;
    cudaFuncSetAttribute(prep_kernel, cudaFuncAttributeMaxDynamicSharedMemorySize, prep_smem);
    cudaFuncSetAttribute(rotary_mma, cudaFuncAttributeMaxDynamicSharedMemorySize, SMEM_SZ);

    prep_kernel<<<96, 256, prep_smem>>>(thetas, pairs, scale, Rm, inv_freq);
    rotary_mma<<<GRID, NTHREADS, SMEM_SZ>>>(x, out);
}

// round 13
// speedup vs baseline: 1.3398x; 1.3398x over previous
#include <cuda_runtime.h>
#include <cuda_fp16.h>
#include <cstdint>
#include <math.h>

#define SEQ   2048
#define HD    128
#define NROT  64
#define NROWS (4 * 2048 * 32)     // 262144 rows of 128
#define TILES64 (NROWS / 64)      // 4096 tiles of 64 rows
#define GRID  304                 // 2 CTAs per SM
#define NTHREADS 256

// main-kernel SMEM layout (bytes) — 96KB per CTA
#define SMEM_B    0               // 32KB: B fragments fp16
#define SMEM_A    32768           // 2 bufs x 16KB (fp16 x-tile, 64 rows)
#define SMEM_ST   65536           // 32KB f32 epilogue stage
#define SMEM_SZ   98304

// ---------------- device globals (allocation-free scratch) ----------------
// B pack: uint4 [kt][wn][c2][lane]; uint4 = (b0,b1) for ntg=wn*4+c2*2 and ntg+1
__device__ uint4  g_Bp[8 * 4 * 2 * 32];
__device__ float2 g_SC[SEQ * 64];             // (sin, cos) per (pos, freq)

// ---------------- helpers ----------------
__device__ __forceinline__ uint32_t smem_u32(const void* p) {
    uint32_t a;
    asm("{ .reg .u64 t; cvta.to.shared.u64 t, %1; cvt.u32.u64 %0, t; }" : "=r"(a) : "l"(p));
    return a;
}

#define LDMATRIX_X4(r, addr) \
    asm volatile("ldmatrix.sync.aligned.m8n8.x4.shared.b16 {%0,%1,%2,%3}, [%4];" \
        : "=r"((r)[0]), "=r"((r)[1]), "=r"((r)[2]), "=r"((r)[3]) : "r"(addr))

#define MMA16816(d, a, b0v, b1v) \
    asm volatile("mma.sync.aligned.m16n8k16.row.col.f32.f16.f16.f32 " \
        "{%0,%1,%2,%3}, {%4,%5,%6,%7}, {%8,%9}, {%0,%1,%2,%3};" \
        : "+f"((d)[0]), "+f"((d)[1]), "+f"((d)[2]), "+f"((d)[3]) \
        : "r"((a)[0]), "r"((a)[1]), "r"((a)[2]), "r"((a)[3]), "r"(b0v), "r"(b1v))

// ---------------- prep kernel ----------------
// block 0     : build M = E1..E64 * Rm by 64 reversed row-rotations on Rm,
//               then pack all B fragments (fp16, mma frag order)
// blocks 1..32: fill the (pos, freq) sin/cos table
__global__ void prep_kernel(const float* __restrict__ thetas,
                            const float* __restrict__ pairs,
                            const float* __restrict__ scale,
                            const float* __restrict__ Rm,
                            const float* __restrict__ inv_freq) {
    const int tid = threadIdx.x;

    if (blockIdx.x > 0) {
        int base = (blockIdx.x - 1) * 256 + tid;     // 0..8191
        #pragma unroll
        for (int r = 0; r < 16; r++) {
            int e = base + r * 8192;
            int s = e >> 6, d = e & 63;
            float a = (float)s * inv_freq[d];
            float sv, cv;
            sincosf(a, &sv, &cv);
            g_SC[e] = make_float2(sv, cv);
        }
        return;
    }

    extern __shared__ float ps[];
    float (*M)[HD] = (float (*)[HD])ps;          // [128][128] = 64KB
    float* cs = ps + HD * HD;                    // cos[64]
    float* sn = cs + 64;                         // sin[64]
    int*   ij = (int*)(sn + 64);                 // i[64], j[64]

    // stage rotation params (parallel sincos)
    if (tid < 64) {
        float th = thetas[tid] * scale[0];
        float s, c;
        sincosf(th, &s, &c);
        cs[tid] = c; sn[tid] = s;
        ij[tid]      = (int)pairs[2 * tid];
        ij[64 + tid] = (int)pairs[2 * tid + 1];
    }
    // load Rm into SMEM (coalesced float4)
    {
        const float4* src = (const float4*)Rm;
        float4* dst = (float4*)ps;
        #pragma unroll
        for (int i = 0; i < 16; i++) dst[tid + i * 256] = src[tid + i * 256];
    }
    __syncthreads();

    // 64 row-rotations in REVERSE order: M <- E_k * M
    // thread t: column c = t & 127, role = t >> 7 (0 -> row i, 1 -> row j)
    {
        const int c    = tid & 127;
        const int role = tid >> 7;
        for (int k = NROT - 1; k >= 0; k--) {
            int   i   = ij[k];
            int   j   = ij[64 + k];
            float cth = cs[k], sth = sn[k];
            float mi = M[i][c];
            float mj = M[j][c];
            __syncthreads();          // all reads done before any write
            float v;
            if (i == j)      v = cth * mi;                       // both roles same
            else if (role == 0) v = cth * mi - sth * mj;         // new row i
            else                v = sth * mi + cth * mj;         // new row j
            M[role == 0 ? i : j][c] = v;
            __syncthreads();
        }
    }

    // pack B fragments: 4096 uint2 entries, 16 per thread
    uint2* bp2 = (uint2*)g_Bp;
    #pragma unroll
    for (int r = 0; r < 16; r++) {
        int e = tid + r * 256;            // 0..4095
        int half = e & 1;
        int lane = (e >> 1) & 31;
        int c2   = (e >> 6) & 1;
        int wn   = (e >> 7) & 3;
        int kt   = (e >> 9) & 7;
        int tq   = lane & 3;
        int nr   = lane >> 2;
        int n    = (wn * 4 + c2 * 2 + half) * 8 + nr;
        int k0   = kt * 16 + tq * 2;
        uint32_t w[4];
        #pragma unroll
        for (int q = 0; q < 4; q++) {
            int k = k0 + (q >> 1) * 8 + (q & 1);
            __half h = __float2half_rn(M[k][n]);
            w[q] = (uint32_t)*(uint16_t*)&h;
        }
        bp2[e] = make_uint2(w[0] | (w[1] << 16), w[2] | (w[3] << 16));
    }
}

// ---------------- main kernel (round-10 champion) ----------------
// A tile SMEM layout (fp16, 16KB, 64 rows): row-major 256B/row, 16B chunks
// XOR-swizzled per 8-row group.

__device__ __forceinline__ void convert_one(float4 v, int g, uint32_t abase) {
    int r = g >> 5;
    int c = g & 31;
    __half2 p01 = __floats2half2_rn(v.x, v.y);
    __half2 p23 = __floats2half2_rn(v.z, v.w);
    uint32_t h01 = *(uint32_t*)&p01;
    uint32_t h23 = *(uint32_t*)&p23;
    uint32_t off = ((uint32_t)r << 8) + (((((uint32_t)c >> 1) ^ (r & 7)) & 15) << 4)
                 + ((c & 1) << 3);
    asm volatile("st.shared.v2.b32 [%0], {%1, %2};" :: "r"(abase + off), "r"(h01), "r"(h23));
}

__global__ void __launch_bounds__(NTHREADS, 2)
rotary_mma(const float* __restrict__ x, float* __restrict__ out) {
    extern __shared__ char smem[];
    const uint32_t sb = smem_u32(smem);
    const int tid  = threadIdx.x;
    const int bid  = blockIdx.x;
    const int warp = tid >> 5;
    const int lane = tid & 31;
    const int wm   = warp >> 2;          // 0..1 : 32-row strip (= seq-pos slot)
    const int wn   = warp & 3;           // 0..3 : 32-col strip
    const int gq   = lane >> 2;          // 0..7
    const int tq   = lane & 3;           // 0..3

    // load B fragments into SMEM (32KB)
    {
        const float4* src = (const float4*)g_Bp;
        float4* dst = (float4*)(smem + SMEM_B);
        #pragma unroll
        for (int i = 0; i < 8; i++) dst[tid + i * NTHREADS] = src[tid + i * NTHREADS];
    }

    const int nt = (TILES64 - bid + GRID - 1) / GRID;
    const float4* x4 = (const float4*)x;
    float4*       o4 = (float4*)out;
    const uint4*  Bf = (const uint4*)(smem + SMEM_B);

    // ldmatrix per-thread address pieces
    const int lr = lane & 15;
    const int lc = lane >> 4;
    const uint32_t sw = lr & 7;
    uint32_t rowoff[2];
    rowoff[0] = (uint32_t)(wm * 32 + lr) << 8;
    rowoff[1] = (uint32_t)(wm * 32 + 16 + lr) << 8;

    // prologue: convert tile 0 into A[0]
    {
        const float4* xs = x4 + (size_t)bid * 2048;
        #pragma unroll
        for (int i = 0; i < 8; i++)
            convert_one(xs[tid + i * NTHREADS], tid + i * NTHREADS, sb + SMEM_A);
    }
    __syncthreads();

    for (int it = 0; it < nt; it++) {
        const int buf  = it & 1;
        const int tile = bid + it * GRID;
        const uint32_t abase = sb + SMEM_A + (uint32_t)buf * 16384;
        const uint32_t anext = sb + SMEM_A + (uint32_t)(buf ^ 1) * 16384;
        const bool have_next = (it + 1 < nt);

        // sin/cos for this warp's position + this thread's 4 freq columns
        float2 scv[4];
        {
            int pos = ((tile << 1) + wm) & (SEQ - 1);
            const float2* scp = g_SC + pos * 64 + wn * 16 + tq;
            #pragma unroll
            for (int n = 0; n < 4; n++) scv[n] = scp[n * 4];
        }

        float acc[2][4][4];
        #pragma unroll
        for (int m = 0; m < 2; m++)
            #pragma unroll
            for (int n = 0; n < 4; n++)
                #pragma unroll
                for (int e = 0; e < 4; e++) acc[m][n][e] = 0.f;

        // pipelined next-tile fetch: 8 float4 per thread
        const float4* xs = x4 + (size_t)(tile + GRID) * 2048;
        float4 q0[8];
        if (have_next) {
            #pragma unroll
            for (int c = 0; c < 4; c++) q0[c] = xs[tid + c * NTHREADS];
        }

        #pragma unroll
        for (int kt = 0; kt < 8; kt++) {
            if (have_next && kt < 4)
                q0[kt + 4] = xs[tid + (kt + 4) * NTHREADS];
            uint32_t A2[2][4];
            const uint32_t choff = ((((uint32_t)(kt * 2 + lc)) ^ sw) & 15) << 4;
            #pragma unroll
            for (int m = 0; m < 2; m++)
                LDMATRIX_X4(A2[m], abase + rowoff[m] + choff);
            #pragma unroll
            for (int c2 = 0; c2 < 2; c2++) {
                uint4 bq = Bf[(((kt * 4 + wn) * 2 + c2) * 32) + lane];
                #pragma unroll
                for (int m = 0; m < 2; m++) {
                    MMA16816(acc[m][c2 * 2],     A2[m], bq.x, bq.y);
                    MMA16816(acc[m][c2 * 2 + 1], A2[m], bq.z, bq.w);
                }
            }
            if (have_next)
                convert_one(q0[kt], tid + kt * NTHREADS, anext);
        }
        __syncthreads();   // A[buf^1] writes done; stage copy-out(it-1) done

        // RoPE + staged transpose (32KB stage, 64 rows)
        {
            float* stage = (float*)(smem + SMEM_ST);
            #pragma unroll
            for (int m = 0; m < 2; m++) {
                #pragma unroll
                for (int h = 0; h < 2; h++) {
                    int row = wm * 32 + m * 16 + h * 8 + gq;
                    int sw2 = row & 7;
                    float* rp = stage + row * 128 + tq;
                    #pragma unroll
                    for (int n = 0; n < 4; n++) {
                        float e = acc[m][n][h * 2];
                        float o = acc[m][n][h * 2 + 1];
                        float s = scv[n].x, c = scv[n].y;
                        int c4 = wn * 4 + n;
                        rp[((c4       ^ sw2) << 2)] = e * c - o * s;   // col d
                        rp[(((16 + c4) ^ sw2) << 2)] = e * s + o * c;  // col 64+d
                    }
                }
            }
        }
        __syncthreads();

        // coalesced copy stage -> out
        {
            const float* stage = (const float*)(smem + SMEM_ST);
            float4* od = o4 + (size_t)tile * 2048;
            #pragma unroll
            for (int i = 0; i < 8; i++) {
                int g = tid + i * NTHREADS;
                int row = g >> 5, c4 = g & 31;
                od[g] = *(const float4*)&stage[row * 128 + ((c4 ^ (row & 7)) << 2)];
            }
        }
        // no sync: next iteration's post-MMA sync orders stage reuse
    }
}

// ---------------- launcher ----------------
extern "C" void kernel_launch(void* const* d_in, const int* in_sizes, int n_in,
                              void* d_out, int out_size) {
    const float* x        = (const float*)d_in[0];
    const float* thetas   = (const float*)d_in[1];
    const float* pairs    = (const float*)d_in[2];
    const float* scale    = (const float*)d_in[3];
    const float* Rm       = (const float*)d_in[4];
    const float* inv_freq = (const float*)d_in[5];
    float*       out      = (float*)d_out;
    (void)in_sizes; (void)n_in; (void)out_size;

    const int prep_smem = (HD * HD + 64 + 64 + 128) * 4;    // 66560
    cudaFuncSetAttribute(prep_kernel, cudaFuncAttributeMaxDynamicSharedMemorySize, prep_smem);
    cudaFuncSetAttribute(rotary_mma, cudaFuncAttributeMaxDynamicSharedMemorySize, SMEM_SZ);

    prep_kernel<<<33, 256, prep_smem>>>(thetas, pairs, scale, Rm, inv_freq);
    rotary_mma<<<GRID, NTHREADS, SMEM_SZ>>>(x, out);
}

// round 14
// speedup vs baseline: 1.3535x; 1.0102x over previous
#include <cuda_runtime.h>
#include <cuda_fp16.h>
#include <cstdint>
#include <math.h>

#define SEQ   2048
#define HD    128
#define NROT  64
#define NROWS (4 * 2048 * 32)     // 262144 rows of 128
#define TILES64 (NROWS / 64)      // 4096 tiles of 64 rows
#define GRID  304                 // 2 CTAs per SM
#define NTHREADS 256

// main-kernel SMEM layout (bytes) — 96KB per CTA
#define SMEM_B    0               // 32KB: B fragments fp16
#define SMEM_A    32768           // 2 bufs x 16KB (fp16 x-tile, 64 rows)
#define SMEM_ST   65536           // 32KB f32 epilogue stage
#define SMEM_SZ   98304

// ---------------- device globals (allocation-free scratch) ----------------
// B pack: uint4 [kt][wn][c2][lane]; uint4 = (b0,b1) for ntg=wn*4+c2*2 and ntg+1
__device__ uint4  g_Bp[8 * 4 * 2 * 32];
__device__ float2 g_SC[SEQ * 64];             // (sin, cos) per (pos, freq)

// ---------------- helpers ----------------
__device__ __forceinline__ uint32_t smem_u32(const void* p) {
    uint32_t a;
    asm("{ .reg .u64 t; cvta.to.shared.u64 t, %1; cvt.u32.u64 %0, t; }" : "=r"(a) : "l"(p));
    return a;
}

#define LDMATRIX_X4(r, addr) \
    asm volatile("ldmatrix.sync.aligned.m8n8.x4.shared.b16 {%0,%1,%2,%3}, [%4];" \
        : "=r"((r)[0]), "=r"((r)[1]), "=r"((r)[2]), "=r"((r)[3]) : "r"(addr))

#define MMA16816(d, a, b0v, b1v) \
    asm volatile("mma.sync.aligned.m16n8k16.row.col.f32.f16.f16.f32 " \
        "{%0,%1,%2,%3}, {%4,%5,%6,%7}, {%8,%9}, {%0,%1,%2,%3};" \
        : "+f"((d)[0]), "+f"((d)[1]), "+f"((d)[2]), "+f"((d)[3]) \
        : "r"((a)[0]), "r"((a)[1]), "r"((a)[2]), "r"((a)[3]), "r"(b0v), "r"(b1v))

// ---------------- prep kernel ----------------
// block 0      : build M = E1..E64 * Rm via BARRIER-FREE column-owner fold,
//                then pack all B fragments (fp16, mma frag order)
// blocks 1..128: fill the (pos, freq) sin/cos table (1024 entries each)
__global__ void prep_kernel(const float* __restrict__ thetas,
                            const float* __restrict__ pairs,
                            const float* __restrict__ scale,
                            const float* __restrict__ Rm,
                            const float* __restrict__ inv_freq) {
    const int tid = threadIdx.x;

    if (blockIdx.x > 0) {
        int base = (blockIdx.x - 1) * 1024 + tid;    // 0..131071
        #pragma unroll
        for (int r = 0; r < 4; r++) {
            int e = base + r * 256;
            int s = e >> 6, d = e & 63;
            float a = (float)s * inv_freq[d];
            float sv, cv;
            sincosf(a, &sv, &cv);
            g_SC[e] = make_float2(sv, cv);
        }
        return;
    }

    extern __shared__ float ps[];
    float (*M)[HD] = (float (*)[HD])ps;          // [128][128] = 64KB
    float* cs = ps + HD * HD;                    // cos[64]
    float* sn = cs + 64;                         // sin[64]
    int*   ij = (int*)(sn + 64);                 // i[64], j[64]

    // stage rotation params (parallel sincos)
    if (tid >= 128 && tid < 192) {
        int k = tid - 128;
        float th = thetas[k] * scale[0];
        float s, c;
        sincosf(th, &s, &c);
        cs[k] = c; sn[k] = s;
        ij[k]      = (int)pairs[2 * k];
        ij[64 + k] = (int)pairs[2 * k + 1];
    }
    // load Rm into SMEM (coalesced float4)
    {
        const float4* src = (const float4*)Rm;
        float4* dst = (float4*)ps;
        #pragma unroll
        for (int i = 0; i < 16; i++) dst[tid + i * 256] = src[tid + i * 256];
    }
    __syncthreads();

    // BARRIER-FREE fold: thread t owns column t. Rotations mix rows within a
    // column only, so M[*][t] is touched exclusively by thread t.
    if (tid < 128) {
        const int c = tid;
        #pragma unroll 4
        for (int k = NROT - 1; k >= 0; k--) {
            int   i   = ij[k];
            int   j   = ij[64 + k];
            float cth = cs[k], sth = sn[k];
            float mi = M[i][c];
            if (i == j) {
                M[i][c] = cth * mi;
            } else {
                float mj = M[j][c];
                M[i][c] = cth * mi - sth * mj;
                M[j][c] = sth * mi + cth * mj;
            }
        }
    }
    __syncthreads();

    // pack B fragments: 4096 uint2 entries, 16 per thread
    uint2* bp2 = (uint2*)g_Bp;
    #pragma unroll
    for (int r = 0; r < 16; r++) {
        int e = tid + r * 256;            // 0..4095
        int half = e & 1;
        int lane = (e >> 1) & 31;
        int c2   = (e >> 6) & 1;
        int wn   = (e >> 7) & 3;
        int kt   = (e >> 9) & 7;
        int tq   = lane & 3;
        int nr   = lane >> 2;
        int n    = (wn * 4 + c2 * 2 + half) * 8 + nr;
        int k0   = kt * 16 + tq * 2;
        uint32_t w[4];
        #pragma unroll
        for (int q = 0; q < 4; q++) {
            int k = k0 + (q >> 1) * 8 + (q & 1);
            __half h = __float2half_rn(M[k][n]);
            w[q] = (uint32_t)*(uint16_t*)&h;
        }
        bp2[e] = make_uint2(w[0] | (w[1] << 16), w[2] | (w[3] << 16));
    }
}

// ---------------- main kernel (champion config) ----------------
// A tile SMEM layout (fp16, 16KB, 64 rows): row-major 256B/row, 16B chunks
// XOR-swizzled per 8-row group.

__device__ __forceinline__ void convert_one(float4 v, int g, uint32_t abase) {
    int r = g >> 5;
    int c = g & 31;
    __half2 p01 = __floats2half2_rn(v.x, v.y);
    __half2 p23 = __floats2half2_rn(v.z, v.w);
    uint32_t h01 = *(uint32_t*)&p01;
    uint32_t h23 = *(uint32_t*)&p23;
    uint32_t off = ((uint32_t)r << 8) + (((((uint32_t)c >> 1) ^ (r & 7)) & 15) << 4)
                 + ((c & 1) << 3);
    asm volatile("st.shared.v2.b32 [%0], {%1, %2};" :: "r"(abase + off), "r"(h01), "r"(h23));
}

__global__ void __launch_bounds__(NTHREADS, 2)
rotary_mma(const float* __restrict__ x, float* __restrict__ out) {
    extern __shared__ char smem[];
    const uint32_t sb = smem_u32(smem);
    const int tid  = threadIdx.x;
    const int bid  = blockIdx.x;
    const int warp = tid >> 5;
    const int lane = tid & 31;
    const int wm   = warp >> 2;          // 0..1 : 32-row strip (= seq-pos slot)
    const int wn   = warp & 3;           // 0..3 : 32-col strip
    const int gq   = lane >> 2;          // 0..7
    const int tq   = lane & 3;           // 0..3

    // load B fragments into SMEM (32KB)
    {
        const float4* src = (const float4*)g_Bp;
        float4* dst = (float4*)(smem + SMEM_B);
        #pragma unroll
        for (int i = 0; i < 8; i++) dst[tid + i * NTHREADS] = src[tid + i * NTHREADS];
    }

    const int nt = (TILES64 - bid + GRID - 1) / GRID;
    const float4* x4 = (const float4*)x;
    float4*       o4 = (float4*)out;
    const uint4*  Bf = (const uint4*)(smem + SMEM_B);

    // ldmatrix per-thread address pieces
    const int lr = lane & 15;
    const int lc = lane >> 4;
    const uint32_t sw = lr & 7;
    uint32_t rowoff[2];
    rowoff[0] = (uint32_t)(wm * 32 + lr) << 8;
    rowoff[1] = (uint32_t)(wm * 32 + 16 + lr) << 8;

    // prologue: convert tile 0 into A[0]
    {
        const float4* xs = x4 + (size_t)bid * 2048;
        #pragma unroll
        for (int i = 0; i < 8; i++)
            convert_one(xs[tid + i * NTHREADS], tid + i * NTHREADS, sb + SMEM_A);
    }
    __syncthreads();

    for (int it = 0; it < nt; it++) {
        const int buf  = it & 1;
        const int tile = bid + it * GRID;
        const uint32_t abase = sb + SMEM_A + (uint32_t)buf * 16384;
        const uint32_t anext = sb + SMEM_A + (uint32_t)(buf ^ 1) * 16384;
        const bool have_next = (it + 1 < nt);

        // sin/cos for this warp's position + this thread's 4 freq columns
        float2 scv[4];
        {
            int pos = ((tile << 1) + wm) & (SEQ - 1);
            const float2* scp = g_SC + pos * 64 + wn * 16 + tq;
            #pragma unroll
            for (int n = 0; n < 4; n++) scv[n] = scp[n * 4];
        }

        float acc[2][4][4];
        #pragma unroll
        for (int m = 0; m < 2; m++)
            #pragma unroll
            for (int n = 0; n < 4; n++)
                #pragma unroll
                for (int e = 0; e < 4; e++) acc[m][n][e] = 0.f;

        // pipelined next-tile fetch: 8 float4 per thread
        const float4* xs = x4 + (size_t)(tile + GRID) * 2048;
        float4 q0[8];
        if (have_next) {
            #pragma unroll
            for (int c = 0; c < 4; c++) q0[c] = xs[tid + c * NTHREADS];
        }

        #pragma unroll
        for (int kt = 0; kt < 8; kt++) {
            if (have_next && kt < 4)
                q0[kt + 4] = xs[tid + (kt + 4) * NTHREADS];
            uint32_t A2[2][4];
            const uint32_t choff = ((((uint32_t)(kt * 2 + lc)) ^ sw) & 15) << 4;
            #pragma unroll
            for (int m = 0; m < 2; m++)
                LDMATRIX_X4(A2[m], abase + rowoff[m] + choff);
            #pragma unroll
            for (int c2 = 0; c2 < 2; c2++) {
                uint4 bq = Bf[(((kt * 4 + wn) * 2 + c2) * 32) + lane];
                #pragma unroll
                for (int m = 0; m < 2; m++) {
                    MMA16816(acc[m][c2 * 2],     A2[m], bq.x, bq.y);
                    MMA16816(acc[m][c2 * 2 + 1], A2[m], bq.z, bq.w);
                }
            }
            if (have_next)
                convert_one(q0[kt], tid + kt * NTHREADS, anext);
        }
        __syncthreads();   // A[buf^1] writes done; stage copy-out(it-1) done

        // RoPE + staged transpose (32KB stage, 64 rows)
        {
            float* stage = (float*)(smem + SMEM_ST);
            #pragma unroll
            for (int m = 0; m < 2; m++) {
                #pragma unroll
                for (int h = 0; h < 2; h++) {
                    int row = wm * 32 + m * 16 + h * 8 + gq;
                    int sw2 = row & 7;
                    float* rp = stage + row * 128 + tq;
                    #pragma unroll
                    for (int n = 0; n < 4; n++) {
                        float e = acc[m][n][h * 2];
                        float o = acc[m][n][h * 2 + 1];
                        float s = scv[n].x, c = scv[n].y;
                        int c4 = wn * 4 + n;
                        rp[((c4       ^ sw2) << 2)] = e * c - o * s;   // col d
                        rp[(((16 + c4) ^ sw2) << 2)] = e * s + o * c;  // col 64+d
                    }
                }
            }
        }
        __syncthreads();

        // coalesced copy stage -> out
        {
            const float* stage = (const float*)(smem + SMEM_ST);
            float4* od = o4 + (size_t)tile * 2048;
            #pragma unroll
            for (int i = 0; i < 8; i++) {
                int g = tid + i * NTHREADS;
                int row = g >> 5, c4 = g & 31;
                od[g] = *(const float4*)&stage[row * 128 + ((c4 ^ (row & 7)) << 2)];
            }
        }
        // no sync: next iteration's post-MMA sync orders stage reuse
    }
}

// ---------------- launcher ----------------
extern "C" void kernel_launch(void* const* d_in, const int* in_sizes, int n_in,
                              void* d_out, int out_size) {
    const float* x        = (const float*)d_in[0];
    const float* thetas   = (const float*)d_in[1];
    const float* pairs    = (const float*)d_in[2];
    const float* scale    = (const float*)d_in[3];
    const float* Rm       = (const float*)d_in[4];
    const float* inv_freq = (const float*)d_in[5];
    float*       out      = (float*)d_out;
    (void)in_sizes; (void)n_in; (void)out_size;

    const int prep_smem = (HD * HD + 64 + 64 + 128) * 4;    // 66560
    cudaFuncSetAttribute(prep_kernel, cudaFuncAttributeMaxDynamicSharedMemorySize, prep_smem);
    cudaFuncSetAttribute(rotary_mma, cudaFuncAttributeMaxDynamicSharedMemorySize, SMEM_SZ);

    prep_kernel<<<129, 256, prep_smem>>>(thetas, pairs, scale, Rm, inv_freq);
    rotary_mma<<<GRID, NTHREADS, SMEM_SZ>>>(x, out);
}